// round 2
// baseline (speedup 1.0000x reference)
#include <cuda_runtime.h>

#define POOL_M 60
#define NC     256
#define HW     3136
#define CHW    (NC * HW)        // 802816
#define NB     64
#define TP     128              // positions per wsum block tile
#define EPSN   1e-8f

typedef unsigned long long ull;

__device__ float g_mavg[POOL_M * NC];
__device__ float g_w[NB * POOL_M];

// ---------------------------------------------------------------------------
// Kernel 1: mean over H*W, one WARP per (m,c) row. Pure warp-shfl reduction.
// ---------------------------------------------------------------------------
__global__ void mean_kernel(const float* __restrict__ pool) {
    const int gw   = (blockIdx.x * blockDim.x + threadIdx.x) >> 5;  // global warp = row
    const int lane = threadIdx.x & 31;
    if (gw >= POOL_M * NC) return;
    const float4* p = reinterpret_cast<const float4*>(pool + (size_t)gw * HW);
    float s = 0.f;
    for (int i = lane; i < HW / 4; i += 32) {       // 784 float4, 24.5 iters
        float4 v = p[i];
        s += (v.x + v.y) + (v.z + v.w);
    }
    #pragma unroll
    for (int o = 16; o > 0; o >>= 1) s += __shfl_down_sync(0xffffffffu, s, o);
    if (lane == 0) g_mavg[gw] = s * (1.0f / (float)HW);
}

// ---------------------------------------------------------------------------
// Kernel 2: cosine + softmax -> g_w[b][m]. 64 blocks, 256 threads.
// 8 warps compute the 60 (dot, norm) pairs in parallel.
// ---------------------------------------------------------------------------
__global__ void cosw_kernel(const float* __restrict__ query) {
    const int b    = blockIdx.x;
    const int t    = threadIdx.x;
    const int wid  = t >> 5;
    const int lane = t & 31;

    __shared__ float sq[NC];
    __shared__ float scos[NB];      // 60 used
    __shared__ float red[8];
    __shared__ float s_qn;

    const float qv = query[b * NC + t];
    sq[t] = qv;

    // q norm (block reduce)
    float s = qv * qv;
    #pragma unroll
    for (int o = 16; o > 0; o >>= 1) s += __shfl_down_sync(0xffffffffu, s, o);
    if (lane == 0) red[wid] = s;
    __syncthreads();
    if (t == 0) {
        float tt = 0.f;
        #pragma unroll
        for (int i = 0; i < 8; i++) tt += red[i];
        s_qn = fmaxf(sqrtf(tt), EPSN);
    }
    __syncthreads();

    // per-m dot + norm, warps handle m = wid, wid+8, ...
    for (int m = wid; m < POOL_M; m += 8) {
        float d = 0.f, n2 = 0.f;
        #pragma unroll
        for (int c = lane; c < NC; c += 32) {
            const float mv = g_mavg[m * NC + c];
            d  = fmaf(mv, sq[c], d);
            n2 = fmaf(mv, mv, n2);
        }
        #pragma unroll
        for (int o = 16; o > 0; o >>= 1) {
            d  += __shfl_down_sync(0xffffffffu, d,  o);
            n2 += __shfl_down_sync(0xffffffffu, n2, o);
        }
        if (lane == 0) scos[m] = d / (s_qn * fmaxf(sqrtf(n2), EPSN));
    }
    __syncthreads();

    // softmax over 60 slots by warp 0 (each lane owns up to 2 values)
    if (wid == 0) {
        const bool hi = (lane + 32) < POOL_M;
        float a  = scos[lane];
        float c2 = hi ? scos[lane + 32] : -1e30f;
        float mx = fmaxf(a, c2);
        #pragma unroll
        for (int o = 16; o > 0; o >>= 1) mx = fmaxf(mx, __shfl_xor_sync(0xffffffffu, mx, o));
        float e1 = __expf(a - mx);
        float e2 = hi ? __expf(c2 - mx) : 0.f;
        float sm = e1 + e2;
        #pragma unroll
        for (int o = 16; o > 0; o >>= 1) sm += __shfl_xor_sync(0xffffffffu, sm, o);
        const float inv = 1.0f / sm;
        g_w[b * POOL_M + lane] = e1 * inv;
        if (hi) g_w[b * POOL_M + lane + 32] = e2 * inv;
    }
}

// ---------------------------------------------------------------------------
// Kernel 3: out[b, pos] = sum_m w[b,m] * pool[m, pos]
// SMEM-tiled: pool tile [60 x 128 pos] + weights [60 x 64] in shared.
// Thread = 1 b x 16 f32x2 positions -> 32 acc registers, no spill.
// ---------------------------------------------------------------------------
__global__ void __launch_bounds__(256)
wsum_kernel(const float* __restrict__ pool, float* __restrict__ out) {
    __shared__ __align__(16) float sp[POOL_M * TP];   // 30720 B
    __shared__ float swt[POOL_M * NB];                // 15360 B

    const int tid = threadIdx.x;
    const long long base = (long long)blockIdx.x * TP;

    // load pool tile: 60 rows x 32 float4 (one warp == one row per iter)
    {
        const float4* pg = reinterpret_cast<const float4*>(pool);
        float4* ps = reinterpret_cast<float4*>(sp);
        #pragma unroll
        for (int i = tid; i < POOL_M * TP / 4; i += 256) {   // 1920
            const int m = i >> 5, v = i & 31;
            ps[i] = pg[((long long)m * CHW + base) / 4 + v];
        }
    }
    // load weights transposed to [m][b]
    for (int i = tid; i < POOL_M * NB; i += 256) {           // 3840
        const int m = i >> 6, bb = i & 63;
        swt[i] = g_w[bb * POOL_M + m];
    }
    __syncthreads();

    const int b   = tid >> 2;            // 0..63
    const int ppb = (tid & 3) * 16;      // f32x2 base within 64 pairs

    ull acc[16];
    #pragma unroll
    for (int j = 0; j < 16; j++) acc[j] = 0ull;

    const ulonglong2* spv = reinterpret_cast<const ulonglong2*>(sp);  // 32 per row
    #pragma unroll 2
    for (int m = 0; m < POOL_M; m++) {
        ull w2;
        {
            const unsigned int wb = __float_as_uint(swt[(m << 6) + b]);
            asm("mov.b64 %0, {%1, %1};" : "=l"(w2) : "r"(wb));
        }
        const ulonglong2* row = spv + (m << 5) + (ppb >> 1);
        #pragma unroll
        for (int k = 0; k < 8; k++) {
            const ulonglong2 pv = row[k];
            asm("fma.rn.f32x2 %0, %1, %2, %0;" : "+l"(acc[2*k])   : "l"(pv.x), "l"(w2));
            asm("fma.rn.f32x2 %0, %1, %2, %0;" : "+l"(acc[2*k+1]) : "l"(pv.y), "l"(w2));
        }
    }

    // store: contiguous 128B region per thread
    ulonglong2* ov = reinterpret_cast<ulonglong2*>(out + (long long)b * CHW + base + ppb * 2);
    #pragma unroll
    for (int k = 0; k < 8; k++) {
        ulonglong2 r; r.x = acc[2*k]; r.y = acc[2*k+1];
        ov[k] = r;
    }
}

// ---------------------------------------------------------------------------
extern "C" void kernel_launch(void* const* d_in, const int* in_sizes, int n_in,
                              void* d_out, int out_size) {
    const float* pool  = (const float*)d_in[0];   // [60,256,56,56]
    const float* query = (const float*)d_in[1];   // [64,256]
    float* out = (float*)d_out;                   // [64,256,56,56]

    mean_kernel<<<(POOL_M * NC) / 8, 256>>>(pool);   // 1920 blocks, warp-per-row
    cosw_kernel<<<NB, 256>>>(query);
    wsum_kernel<<<CHW / TP, 256>>>(pool, out);
}

// round 3
// speedup vs baseline: 4.4577x; 4.4577x over previous
#include <cuda_runtime.h>

#define POOL_M 60
#define NC     256
#define HW     3136
#define CHW    (NC * HW)        // 802816
#define NB     64
#define EPSN   1e-8f

typedef unsigned long long ull;

__device__ float g_mavg[POOL_M * NC];
__device__ float g_w[NB * POOL_M];

// ---------------------------------------------------------------------------
// Kernel 1: mean over H*W, one WARP per (m,c) row. Pure warp-shfl reduction.
// ---------------------------------------------------------------------------
__global__ void mean_kernel(const float* __restrict__ pool) {
    const int gw   = (blockIdx.x * blockDim.x + threadIdx.x) >> 5;  // row
    const int lane = threadIdx.x & 31;
    if (gw >= POOL_M * NC) return;
    const float4* p = reinterpret_cast<const float4*>(pool + (size_t)gw * HW);
    float s0 = 0.f, s1 = 0.f;
    #pragma unroll 4
    for (int i = lane; i < HW / 4 - 32; i += 64) {      // two independent streams
        float4 a = p[i];
        float4 b = p[i + 32];
        s0 += (a.x + a.y) + (a.z + a.w);
        s1 += (b.x + b.y) + (b.z + b.w);
    }
    // tail (784 = 12*64 + 16): indices 768..783
    if (lane < 16) {
        float4 a = p[768 + lane];
        s0 += (a.x + a.y) + (a.z + a.w);
    }
    float s = s0 + s1;
    #pragma unroll
    for (int o = 16; o > 0; o >>= 1) s += __shfl_down_sync(0xffffffffu, s, o);
    if (lane == 0) g_mavg[gw] = s * (1.0f / (float)HW);
}

// ---------------------------------------------------------------------------
// Kernel 2: cosine + softmax -> g_w[b][m]. 64 blocks x 256 threads. Tiny.
// ---------------------------------------------------------------------------
__global__ void cosw_kernel(const float* __restrict__ query) {
    const int b    = blockIdx.x;
    const int t    = threadIdx.x;
    const int wid  = t >> 5;
    const int lane = t & 31;

    __shared__ float sq[NC];
    __shared__ float scos[NB];
    __shared__ float red[8];
    __shared__ float s_qn;

    const float qv = query[b * NC + t];
    sq[t] = qv;

    float s = qv * qv;
    #pragma unroll
    for (int o = 16; o > 0; o >>= 1) s += __shfl_down_sync(0xffffffffu, s, o);
    if (lane == 0) red[wid] = s;
    __syncthreads();
    if (t == 0) {
        float tt = 0.f;
        #pragma unroll
        for (int i = 0; i < 8; i++) tt += red[i];
        s_qn = fmaxf(sqrtf(tt), EPSN);
    }
    __syncthreads();

    for (int m = wid; m < POOL_M; m += 8) {
        float d = 0.f, n2 = 0.f;
        #pragma unroll
        for (int c = lane; c < NC; c += 32) {
            const float mv = g_mavg[m * NC + c];
            d  = fmaf(mv, sq[c], d);
            n2 = fmaf(mv, mv, n2);
        }
        #pragma unroll
        for (int o = 16; o > 0; o >>= 1) {
            d  += __shfl_down_sync(0xffffffffu, d,  o);
            n2 += __shfl_down_sync(0xffffffffu, n2, o);
        }
        if (lane == 0) scos[m] = d / (s_qn * fmaxf(sqrtf(n2), EPSN));
    }
    __syncthreads();

    if (wid == 0) {
        const bool hi = (lane + 32) < POOL_M;
        float a  = scos[lane];
        float c2 = hi ? scos[lane + 32] : -1e30f;
        float mx = fmaxf(a, c2);
        #pragma unroll
        for (int o = 16; o > 0; o >>= 1) mx = fmaxf(mx, __shfl_xor_sync(0xffffffffu, mx, o));
        float e1 = __expf(a - mx);
        float e2 = hi ? __expf(c2 - mx) : 0.f;
        float sm = e1 + e2;
        #pragma unroll
        for (int o = 16; o > 0; o >>= 1) sm += __shfl_xor_sync(0xffffffffu, sm, o);
        const float inv = 1.0f / sm;
        g_w[b * POOL_M + lane] = e1 * inv;
        if (hi) g_w[b * POOL_M + lane + 32] = e2 * inv;
    }
}

// ---------------------------------------------------------------------------
// Kernel 3: out[b, pos] = sum_m w[b,m] * pool[m, pos]
// Block = 256 thr = 8 warps; every warp covers the SAME 128 positions
// (lane*4 each, one LDG.128 per m) for its own octet of 8 b-values.
// 16 ull accumulators/thread, FFMA2 math, broadcast LDS.64 weights.
// Pool hits DRAM once per block (7/8 warps hit L1).
// ---------------------------------------------------------------------------
__global__ void __launch_bounds__(256)
wsum_kernel(const float* __restrict__ pool, float* __restrict__ out) {
    __shared__ ull sw[POOL_M * NB];          // [m][b] duplicated (w,w) pairs, 30 KB
    const int tid = threadIdx.x;
    for (int i = tid; i < POOL_M * NB; i += 256) {
        const int m = i >> 6, bb = i & 63;
        const unsigned int wb = __float_as_uint(g_w[bb * POOL_M + m]);
        ull w2; asm("mov.b64 %0, {%1, %1};" : "=l"(w2) : "r"(wb));
        sw[i] = w2;
    }
    __syncthreads();

    const int warp = tid >> 5;
    const int lane = tid & 31;
    const int b0   = warp * 8;
    const long long pos = (long long)blockIdx.x * 128 + lane * 4;

    ull acc[8][2];
    #pragma unroll
    for (int j = 0; j < 8; j++) { acc[j][0] = 0ull; acc[j][1] = 0ull; }

    const ulonglong2* pv = reinterpret_cast<const ulonglong2*>(pool + pos);
    #pragma unroll 4
    for (int m = 0; m < POOL_M; m++) {
        const ulonglong2 p = pv[(long long)m * (CHW / 4)];
        const ull* wrow = &sw[(m << 6) + b0];
        #pragma unroll
        for (int j = 0; j < 8; j++) {
            const ull w2 = wrow[j];
            asm("fma.rn.f32x2 %0, %1, %2, %0;" : "+l"(acc[j][0]) : "l"(p.x), "l"(w2));
            asm("fma.rn.f32x2 %0, %1, %2, %0;" : "+l"(acc[j][1]) : "l"(p.y), "l"(w2));
        }
    }

    #pragma unroll
    for (int j = 0; j < 8; j++) {
        ulonglong2 r; r.x = acc[j][0]; r.y = acc[j][1];
        *reinterpret_cast<ulonglong2*>(out + (long long)(b0 + j) * CHW + pos) = r;
    }
}

// ---------------------------------------------------------------------------
extern "C" void kernel_launch(void* const* d_in, const int* in_sizes, int n_in,
                              void* d_out, int out_size) {
    const float* pool  = (const float*)d_in[0];   // [60,256,56,56]
    const float* query = (const float*)d_in[1];   // [64,256]
    float* out = (float*)d_out;                   // [64,256,56,56]

    mean_kernel<<<(POOL_M * NC) / 8, 256>>>(pool);
    cosw_kernel<<<NB, 256>>>(query);
    wsum_kernel<<<CHW / 128, 256>>>(pool, out);
}

// round 6
// speedup vs baseline: 7.8526x; 1.7616x over previous
#include <cuda_runtime.h>
#include <cstdint>

#define POOL_M 60
#define NC     256
#define HW     3136
#define CHW    (NC * HW)        // 802816
#define NB     64
#define KP     64               // padded K for MMA
#define PW     68               // sW pitch (floats)
#define PP     72               // sP pitch (floats)
#define EPSN   1e-8f

__device__ float g_mavg[POOL_M * NC];
__device__ float g_w[NB * POOL_M];

// ---------------------------------------------------------------------------
// Kernel 1: mean over H*W, one WARP per (m,c) row.
// ---------------------------------------------------------------------------
__global__ void mean_kernel(const float* __restrict__ pool) {
    const int gw   = (blockIdx.x * blockDim.x + threadIdx.x) >> 5;
    const int lane = threadIdx.x & 31;
    if (gw >= POOL_M * NC) return;
    const float4* p = reinterpret_cast<const float4*>(pool + (size_t)gw * HW);
    float s0 = 0.f, s1 = 0.f;
    #pragma unroll 4
    for (int i = lane; i < HW / 4 - 32; i += 64) {
        float4 a = p[i];
        float4 b = p[i + 32];
        s0 += (a.x + a.y) + (a.z + a.w);
        s1 += (b.x + b.y) + (b.z + b.w);
    }
    if (lane < 16) {
        float4 a = p[768 + lane];
        s0 += (a.x + a.y) + (a.z + a.w);
    }
    float s = s0 + s1;
    #pragma unroll
    for (int o = 16; o > 0; o >>= 1) s += __shfl_down_sync(0xffffffffu, s, o);
    if (lane == 0) g_mavg[gw] = s * (1.0f / (float)HW);
}

// ---------------------------------------------------------------------------
// Kernel 2: cosine + softmax -> g_w[b][m].
// ---------------------------------------------------------------------------
__global__ void cosw_kernel(const float* __restrict__ query) {
    const int b    = blockIdx.x;
    const int t    = threadIdx.x;
    const int wid  = t >> 5;
    const int lane = t & 31;

    __shared__ float sq[NC];
    __shared__ float scos[NB];
    __shared__ float red[8];
    __shared__ float s_qn;

    const float qv = query[b * NC + t];
    sq[t] = qv;

    float s = qv * qv;
    #pragma unroll
    for (int o = 16; o > 0; o >>= 1) s += __shfl_down_sync(0xffffffffu, s, o);
    if (lane == 0) red[wid] = s;
    __syncthreads();
    if (t == 0) {
        float tt = 0.f;
        #pragma unroll
        for (int i = 0; i < 8; i++) tt += red[i];
        s_qn = fmaxf(sqrtf(tt), EPSN);
    }
    __syncthreads();

    for (int m = wid; m < POOL_M; m += 8) {
        float d = 0.f, n2 = 0.f;
        #pragma unroll
        for (int c = lane; c < NC; c += 32) {
            const float mv = g_mavg[m * NC + c];
            d  = fmaf(mv, sq[c], d);
            n2 = fmaf(mv, mv, n2);
        }
        #pragma unroll
        for (int o = 16; o > 0; o >>= 1) {
            d  += __shfl_down_sync(0xffffffffu, d,  o);
            n2 += __shfl_down_sync(0xffffffffu, n2, o);
        }
        if (lane == 0) scos[m] = d / (s_qn * fmaxf(sqrtf(n2), EPSN));
    }
    __syncthreads();

    if (wid == 0) {
        const bool hi = (lane + 32) < POOL_M;
        float a  = scos[lane];
        float c2 = hi ? scos[lane + 32] : -1e30f;
        float mx = fmaxf(a, c2);
        #pragma unroll
        for (int o = 16; o > 0; o >>= 1) mx = fmaxf(mx, __shfl_xor_sync(0xffffffffu, mx, o));
        float e1 = __expf(a - mx);
        float e2 = hi ? __expf(c2 - mx) : 0.f;
        float sm = e1 + e2;
        #pragma unroll
        for (int o = 16; o > 0; o >>= 1) sm += __shfl_xor_sync(0xffffffffu, sm, o);
        const float inv = 1.0f / sm;
        g_w[b * POOL_M + lane] = e1 * inv;
        if (hi) g_w[b * POOL_M + lane + 32] = e2 * inv;
    }
}

// ---------------------------------------------------------------------------
// Kernel 3: out = W @ P via m16n8k8 TF32 tensor-core MMA, 3xTF32 split for
// fp32-grade accuracy. Block tile: 64 b x 64 pos, K = 64 (60 + zero pad).
// 8 warps = 4 b-rows (16 b) x 2 pos-cols (32 pos); warp = 4 n-tiles of 8.
// ---------------------------------------------------------------------------
__device__ __forceinline__ void mma_tf32(float* d, const uint32_t* a,
                                         uint32_t b0, uint32_t b1) {
    asm volatile(
        "mma.sync.aligned.m16n8k8.row.col.f32.tf32.tf32.f32 "
        "{%0,%1,%2,%3}, {%4,%5,%6,%7}, {%8,%9}, {%0,%1,%2,%3};"
        : "+f"(d[0]), "+f"(d[1]), "+f"(d[2]), "+f"(d[3])
        : "r"(a[0]), "r"(a[1]), "r"(a[2]), "r"(a[3]), "r"(b0), "r"(b1));
}

__device__ __forceinline__ uint32_t f32_to_tf32(float x) {
    uint32_t r;
    asm("cvt.rna.tf32.f32 %0, %1;" : "=r"(r) : "f"(x));
    return r;
}

__global__ void __launch_bounds__(256)
wsum_kernel(const float* __restrict__ pool, float* __restrict__ out) {
    __shared__ __align__(16) float sW[NB * PW];   // [b][k]  17408 B
    __shared__ __align__(16) float sP[KP * PP];   // [k][pos] 18432 B

    const int tid  = threadIdx.x;
    const int warp = tid >> 5;
    const int lane = tid & 31;
    const int g    = lane >> 2;      // 0..7
    const int tg   = lane & 3;       // 0..3
    const int brow = warp & 3;       // 16-b rows
    const int pcol = warp >> 2;      // 0..1  (32-pos cols)
    const long long posbase = (long long)blockIdx.x * 64;

    // stage weights [64 b][64 k] (k>=60 zero)
    for (int i = tid; i < NB * KP; i += 256) {
        const int b = i >> 6, k = i & 63;
        sW[b * PW + k] = (k < POOL_M) ? g_w[b * POOL_M + k] : 0.f;
    }
    // stage pool tile [64 k][64 pos] (k>=60 zero), 16 float4 per row
    {
        const int m = tid >> 4;          // 0..15, +16 per iter
        const int v = tid & 15;
        #pragma unroll
        for (int r = 0; r < 4; r++) {
            const int mm = m + r * 16;
            float4 val = make_float4(0.f, 0.f, 0.f, 0.f);
            if (mm < POOL_M)
                val = *reinterpret_cast<const float4*>(pool + (long long)mm * CHW + posbase + v * 4);
            *reinterpret_cast<float4*>(&sP[mm * PP + v * 4]) = val;
        }
    }
    __syncthreads();

    float acc[4][4];
    #pragma unroll
    for (int nt = 0; nt < 4; nt++)
        #pragma unroll
        for (int j = 0; j < 4; j++) acc[nt][j] = 0.f;

    const float* pW = &sW[(brow * 16 + g) * PW + tg];
    const float* pP = &sP[tg * PP + pcol * 32 + g];

    #pragma unroll
    for (int kb = 0; kb < 8; kb++) {
        // A fragment (weights) hi/lo
        float a0 = pW[kb * 8];
        float a1 = pW[kb * 8 + 8 * PW];
        float a2 = pW[kb * 8 + 4];
        float a3 = pW[kb * 8 + 4 + 8 * PW];
        uint32_t ahi[4], alo[4];
        ahi[0] = f32_to_tf32(a0); alo[0] = __float_as_uint(a0 - __uint_as_float(ahi[0]));
        ahi[1] = f32_to_tf32(a1); alo[1] = __float_as_uint(a1 - __uint_as_float(ahi[1]));
        ahi[2] = f32_to_tf32(a2); alo[2] = __float_as_uint(a2 - __uint_as_float(ahi[2]));
        ahi[3] = f32_to_tf32(a3); alo[3] = __float_as_uint(a3 - __uint_as_float(ahi[3]));

        #pragma unroll
        for (int nt = 0; nt < 4; nt++) {
            const float b0f = pP[(kb * 8)     * PP + nt * 8];
            const float b1f = pP[(kb * 8 + 4) * PP + nt * 8];
            const uint32_t bhi0 = f32_to_tf32(b0f);
            const uint32_t bhi1 = f32_to_tf32(b1f);
            const uint32_t blo0 = __float_as_uint(b0f - __uint_as_float(bhi0));
            const uint32_t blo1 = __float_as_uint(b1f - __uint_as_float(bhi1));
            mma_tf32(acc[nt], ahi, bhi0, bhi1);
            mma_tf32(acc[nt], ahi, blo0, blo1);
            mma_tf32(acc[nt], alo, bhi0, bhi1);
        }
    }

    // epilogue: c0,c1 -> (row g, col 2tg..2tg+1); c2,c3 -> row g+8
    const int bq = brow * 16 + g;
    const long long pb = posbase + pcol * 32 + tg * 2;
    #pragma unroll
    for (int nt = 0; nt < 4; nt++) {
        float2 lo; lo.x = acc[nt][0]; lo.y = acc[nt][1];
        float2 hi; hi.x = acc[nt][2]; hi.y = acc[nt][3];
        *reinterpret_cast<float2*>(out + (long long)bq * CHW + pb + nt * 8)       = lo;
        *reinterpret_cast<float2*>(out + (long long)(bq + 8) * CHW + pb + nt * 8) = hi;
    }
}

// ---------------------------------------------------------------------------
extern "C" void kernel_launch(void* const* d_in, const int* in_sizes, int n_in,
                              void* d_out, int out_size) {
    const float* pool  = (const float*)d_in[0];   // [60,256,56,56]
    const float* query = (const float*)d_in[1];   // [64,256]
    float* out = (float*)d_out;                   // [64,256,56,56]

    mean_kernel<<<(POOL_M * NC) / 8, 256>>>(pool);
    cosw_kernel<<<NB, 256>>>(query);
    wsum_kernel<<<CHW / 64, 256>>>(pool, out);
}